// round 11
// baseline (speedup 1.0000x reference)
#include <cuda_runtime.h>
#include <cuda_fp16.h>
#include <math.h>
#include <stdint.h>

// ---------------- problem constants ----------------
#define N_NODES   100000
#define N_EDGES   3200000
#define N_FEAT    128
#define HIDDEN    64
#define N_CLASSES 3
#define N_GRAPHS  512
#define BN_EPS    1e-5f

#define SCAN_BS   1024
#define SCAN_NB   ((N_NODES + SCAN_BS - 1) / SCAN_BS)   // 98

// ---------------- device scratch (no allocation allowed) ----------------
__device__ __align__(16) __half g_hs[(size_t)N_NODES * HIDDEN];  // dinv-scaled fp16 rows (conv gather input)
__device__ __align__(16) float  g_h2[(size_t)N_NODES * HIDDEN];  // conv output fp32 (gemm2 input / pool input)
__device__ int      g_csr_src[N_EDGES];
__device__ uint32_t g_dp[N_EDGES];    // packed (dst<<15 | pos) recorded by hist
__device__ int      g_ptr[N_NODES];   // block-local exclusive scan (finalized via g_bsum)
__device__ int      g_cnt[N_NODES];   // in-degree (no self loop)
__device__ float    g_dinv[N_NODES];
__device__ int      g_bsum[SCAN_NB + 1];
__device__ int      g_gstart[N_GRAPHS + 1];
__device__ __align__(16) float g_bnA1[HIDDEN], g_bnB1[HIDDEN], g_bnA2[HIDDEN], g_bnB2[HIDDEN];
__device__ int      g_idx64;          // 1 if edge/batch buffers are int64, 0 if int32

__device__ __forceinline__ int load_idx(const void* p, size_t i) {
    if (g_idx64) return (int)((const long long*)p)[i];
    return ((const int*)p)[i];
}

__device__ __forceinline__ uint32_t f2tf32(float x) {
    uint32_t y;
    asm("cvt.rna.tf32.f32 %0, %1;" : "=r"(y) : "f"(x));
    return y;
}

__device__ __forceinline__ int ptr_of(int n) {
    if (n >= N_NODES) return N_EDGES;
    return g_ptr[n] + g_bsum[n >> 10];
}

// ---------------- init: zero degree counters ----------------
__global__ void k_init() {
    int i = blockIdx.x * blockDim.x + threadIdx.x;
    if (i < N_NODES) g_cnt[i] = 0;
}

// ---------------- fused prep (single block, 512 thr): detect + graph starts + bnprep ----------------
__global__ void k_pre(const void* __restrict__ ei, const void* __restrict__ batch,
                      const float* b1, const float* gm1, const float* bt1,
                      const float* rm1, const float* rv1,
                      const float* b2, const float* gm2, const float* bt2,
                      const float* rm2, const float* rv2) {
    int t = threadIdx.x;
    // phase 1: parallel dtype detect
    if (t < 32) {
        const long long* p = (const long long*)ei;
        int bad = 0;
        if (t < 16) {
            long long v = p[t];
            bad = (v < 0 || v >= N_NODES);
        }
        unsigned m = __ballot_sync(0xffffffffu, bad);
        if (t == 0) g_idx64 = (m == 0u);
    }
    __syncthreads();
    // phase 2: graph start offsets via binary search (batch sorted)
    if (t < N_GRAPHS) {
        int g = t;
        int lo = 0, hi = N_NODES;
        while (lo < hi) { int m = (lo + hi) >> 1; if (load_idx(batch, m) < g) lo = m + 1; else hi = m; }
        g_gstart[t] = lo;
    }
    if (t == 0) g_gstart[N_GRAPHS] = N_NODES;
    // phase 3: fold bias+BN into per-feature affine
    if (t < HIDDEN) {
        float a1 = gm1[t] * rsqrtf(rv1[t] + BN_EPS);
        g_bnA1[t] = a1;
        g_bnB1[t] = (b1[t] - rm1[t]) * a1 + bt1[t];
        float a2 = gm2[t] * rsqrtf(rv2[t] + BN_EPS);
        g_bnA2[t] = a2;
        g_bnB2[t] = (b2[t] - rm2[t]) * a2 + bt2[t];
    }
}

// ---------------- histogram of dst; record packed (dst,pos) ----------------
__global__ void k_hist(const void* __restrict__ ei) {
    int e = blockIdx.x * blockDim.x + threadIdx.x;
    if (e < N_EDGES) {
        int d = load_idx(ei, (size_t)N_EDGES + e);
        uint32_t pos = (uint32_t)atomicAdd(&g_cnt[d], 1);
        g_dp[e] = ((uint32_t)d << 15) | pos;
    }
}

// ---------------- scan: block-local exclusive (+dinv fused), then block-sum scan ----------------
__global__ void k_scanA() {
    __shared__ int sm[SCAN_BS];
    int i = blockIdx.x * SCAN_BS + threadIdx.x;
    int v = (i < N_NODES) ? g_cnt[i] : 0;
    if (i < N_NODES) g_dinv[i] = rsqrtf((float)(v + 1));
    sm[threadIdx.x] = v;
    __syncthreads();
    for (int off = 1; off < SCAN_BS; off <<= 1) {
        int t = (threadIdx.x >= off) ? sm[threadIdx.x - off] : 0;
        __syncthreads();
        sm[threadIdx.x] += t;
        __syncthreads();
    }
    if (i < N_NODES) g_ptr[i] = sm[threadIdx.x] - v;
    if (threadIdx.x == SCAN_BS - 1) g_bsum[blockIdx.x] = sm[SCAN_BS - 1];
}

__global__ void k_scanB() {
    __shared__ int sm[128];
    int t = threadIdx.x;
    int v = (t < SCAN_NB) ? g_bsum[t] : 0;
    sm[t] = v;
    __syncthreads();
    for (int off = 1; off < 128; off <<= 1) {
        int u = (t >= off) ? sm[t - off] : 0;
        __syncthreads();
        sm[t] += u;
        __syncthreads();
    }
    if (t < SCAN_NB) g_bsum[t] = sm[t] - v;
}

// ---------------- fill CSR: atomic-free ----------------
__global__ void k_fill(const void* __restrict__ ei) {
    int e = blockIdx.x * blockDim.x + threadIdx.x;
    if (e < N_EDGES) {
        int s = load_idx(ei, e);
        uint32_t dp = g_dp[e];
        int d   = (int)(dp >> 15);
        int pos = (int)(dp & 0x7fffu);
        g_csr_src[g_ptr[d] + g_bsum[d >> 10] + pos] = s;
    }
}

// ---------------- tensor-core GEMM (tf32 mma.sync m16n8k8) ----------------
// g_hs[M,64](fp16) = (A[M,K] @ W[K,64]) * dinv[row]
template<int K, int SRC>
__global__ void k_gemm_tc(const float* __restrict__ Aext, const float* __restrict__ W,
                          int M) {
    __shared__ uint32_t sA[64 * 68];
    __shared__ uint32_t sW[64 * 72];
    const float* A = (SRC == 0) ? Aext : g_h2;
    int row0 = blockIdx.x * 64;
    int t    = threadIdx.x;
    int w    = t >> 5;
    int lane = t & 31;
    int g    = lane >> 2;
    int tig  = lane & 3;

    float acc[8][4];
    #pragma unroll
    for (int nt = 0; nt < 8; nt++)
        #pragma unroll
        for (int j = 0; j < 4; j++) acc[nt][j] = 0.0f;

    for (int k0 = 0; k0 < K; k0 += 64) {
        for (int i = t; i < 64 * 16; i += 128) {
            int r = i >> 4;
            int c = (i & 15) << 2;
            float4 v = *(const float4*)(W + (size_t)(k0 + r) * 64 + c);
            sW[r * 72 + c + 0] = f2tf32(v.x);
            sW[r * 72 + c + 1] = f2tf32(v.y);
            sW[r * 72 + c + 2] = f2tf32(v.z);
            sW[r * 72 + c + 3] = f2tf32(v.w);
        }
        for (int i = t; i < 64 * 16; i += 128) {
            int r = i >> 4;
            int c = (i & 15) << 2;
            int row = row0 + r;
            float4 v = make_float4(0.f, 0.f, 0.f, 0.f);
            if (row < M) v = *(const float4*)(A + (size_t)row * K + k0 + c);
            sA[r * 68 + c + 0] = f2tf32(v.x);
            sA[r * 68 + c + 1] = f2tf32(v.y);
            sA[r * 68 + c + 2] = f2tf32(v.z);
            sA[r * 68 + c + 3] = f2tf32(v.w);
        }
        __syncthreads();
        #pragma unroll
        for (int kc = 0; kc < 8; kc++) {
            int kk = kc * 8;
            uint32_t a0 = sA[(w * 16 + g)     * 68 + kk + tig];
            uint32_t a1 = sA[(w * 16 + g + 8) * 68 + kk + tig];
            uint32_t a2 = sA[(w * 16 + g)     * 68 + kk + tig + 4];
            uint32_t a3 = sA[(w * 16 + g + 8) * 68 + kk + tig + 4];
            #pragma unroll
            for (int nt = 0; nt < 8; nt++) {
                uint32_t b0 = sW[(kk + tig)     * 72 + nt * 8 + g];
                uint32_t b1 = sW[(kk + tig + 4) * 72 + nt * 8 + g];
                asm volatile(
                    "mma.sync.aligned.m16n8k8.row.col.f32.tf32.tf32.f32 "
                    "{%0,%1,%2,%3}, {%4,%5,%6,%7}, {%8,%9}, {%0,%1,%2,%3};"
                    : "+f"(acc[nt][0]), "+f"(acc[nt][1]), "+f"(acc[nt][2]), "+f"(acc[nt][3])
                    : "r"(a0), "r"(a1), "r"(a2), "r"(a3), "r"(b0), "r"(b1));
            }
        }
        __syncthreads();
    }
    int r0 = row0 + w * 16 + g;
    int r1 = r0 + 8;
    if (r0 < M) {
        float d = g_dinv[r0];
        #pragma unroll
        for (int nt = 0; nt < 8; nt++) {
            __half2 v = __floats2half2_rn(acc[nt][0] * d, acc[nt][1] * d);
            *(__half2*)(g_hs + (size_t)r0 * 64 + nt * 8 + 2 * tig) = v;
        }
    }
    if (r1 < M) {
        float d = g_dinv[r1];
        #pragma unroll
        for (int nt = 0; nt < 8; nt++) {
            __half2 v = __floats2half2_rn(acc[nt][2] * d, acc[nt][3] * d);
            *(__half2*)(g_hs + (size_t)r1 * 64 + nt * 8 + 2 * tig) = v;
        }
    }
}

// ---------------- conv (pull, warp-per-node, 2 edges/iter, 8B loads) ----------------
// reads g_hs (fp16, dinv-scaled); writes g_h2[n] = relu(dinv[n]*(sum+self)*A + B)
// LAYER selects the folded BN affine.
template<int LAYER>
__global__ void k_conv() {
    int warp = (blockIdx.x * blockDim.x + threadIdx.x) >> 5;
    int lane = threadIdx.x & 31;
    if (warp >= N_NODES) return;
    int n = warp;
    int h = lane >> 4;     // half-warp: which edge of the pair
    int q = lane & 15;     // feature quad: features 4q..4q+3
    const uint2* hin = (const uint2*)g_hs;   // row = 16 uint2 (64 halves)

    float4 acc = make_float4(0.f, 0.f, 0.f, 0.f);
    int start = ptr_of(n);
    int end   = ptr_of(n + 1);

    int e = start;
    for (; e + 32 <= end; e += 32) {
        int s = g_csr_src[e + lane];
        #pragma unroll
        for (int jj = 0; jj < 16; jj++) {
            int sj = __shfl_sync(0xffffffffu, s, 2 * jj + h);
            uint2 raw = hin[(size_t)sj * 16 + q];
            __half2 p0 = *reinterpret_cast<__half2*>(&raw.x);
            __half2 p1 = *reinterpret_cast<__half2*>(&raw.y);
            float2 f0 = __half22float2(p0);
            float2 f1 = __half22float2(p1);
            acc.x += f0.x; acc.y += f0.y; acc.z += f1.x; acc.w += f1.y;
        }
    }
    int rem = end - e;
    if (rem > 0) {
        int s = (lane < rem) ? g_csr_src[e + lane] : 0;
        int iters = (rem + 1) >> 1;
        for (int jj = 0; jj < iters; jj++) {
            int idx = 2 * jj + h;
            int sj = __shfl_sync(0xffffffffu, s, idx & 31);
            if (idx < rem) {
                uint2 raw = hin[(size_t)sj * 16 + q];
                __half2 p0 = *reinterpret_cast<__half2*>(&raw.x);
                __half2 p1 = *reinterpret_cast<__half2*>(&raw.y);
                float2 f0 = __half22float2(p0);
                float2 f1 = __half22float2(p1);
                acc.x += f0.x; acc.y += f0.y; acc.z += f1.x; acc.w += f1.y;
            }
        }
    }
    // combine half-warps: lane q gets acc(h=0) + acc(h=1)
    float ox = __shfl_xor_sync(0xffffffffu, acc.x, 16);
    float oy = __shfl_xor_sync(0xffffffffu, acc.y, 16);
    float oz = __shfl_xor_sync(0xffffffffu, acc.z, 16);
    float ow = __shfl_xor_sync(0xffffffffu, acc.w, 16);
    if (h == 0) {
        acc.x += ox; acc.y += oy; acc.z += oz; acc.w += ow;
        // self loop (hs[n] already carries dinv[n])
        uint2 raw = hin[(size_t)n * 16 + q];
        __half2 p0 = *reinterpret_cast<__half2*>(&raw.x);
        __half2 p1 = *reinterpret_cast<__half2*>(&raw.y);
        float2 f0 = __half22float2(p0);
        float2 f1 = __half22float2(p1);
        acc.x += f0.x; acc.y += f0.y; acc.z += f1.x; acc.w += f1.y;

        float dn = g_dinv[n];
        const float* bnA = (LAYER == 1) ? g_bnA1 : g_bnA2;
        const float* bnB = (LAYER == 1) ? g_bnB1 : g_bnB2;
        float4 A = ((const float4*)bnA)[q];
        float4 B = ((const float4*)bnB)[q];
        float4 v;
        v.x = fmaxf(acc.x * dn * A.x + B.x, 0.f);
        v.y = fmaxf(acc.y * dn * A.y + B.y, 0.f);
        v.z = fmaxf(acc.z * dn * A.z + B.z, 0.f);
        v.w = fmaxf(acc.w * dn * A.w + B.w, 0.f);
        ((float4*)g_h2)[(size_t)n * 16 + q] = v;
    }
}

// ---------------- pool + classifier (block per graph, atomic-free) ----------------
__global__ void k_pool(const float* __restrict__ Wc, const float* __restrict__ bc,
                       float* __restrict__ out) {
    __shared__ float sm[256];
    int g = blockIdx.x;
    int t = threadIdx.x;
    int f   = t & 63;
    int grp = t >> 6;    // 4 row groups
    int s  = g_gstart[g];
    int eN = g_gstart[g + 1];
    float sum = 0.0f;
    for (int n = s + grp; n < eN; n += 4) sum += g_h2[(size_t)n * 64 + f];
    sm[t] = sum;
    __syncthreads();
    if (t < 64) {
        float tot = sm[t] + sm[t + 64] + sm[t + 128] + sm[t + 192];
        sm[t] = tot * (1.0f / fmaxf((float)(eN - s), 1.0f));
    }
    __syncthreads();
    if (t < N_CLASSES) {
        float o = bc[t];
        #pragma unroll
        for (int f2 = 0; f2 < HIDDEN; f2++) o += sm[f2] * Wc[f2 * N_CLASSES + t];
        out[g * N_CLASSES + t] = o;
    }
}

// ---------------- launch ----------------
extern "C" void kernel_launch(void* const* d_in, const int* in_sizes, int n_in,
                              void* d_out, int out_size) {
    const float *x = 0, *W1 = 0, *W2 = 0, *Wc = 0, *bc = 0;
    const void  *ei = 0, *batch = 0;
    const float* v64[10] = {0};
    int n64 = 0;
    for (int i = 0; i < n_in; i++) {
        switch (in_sizes[i]) {
            case N_NODES * N_FEAT:   x     = (const float*)d_in[i]; break;
            case 2 * N_EDGES:        ei    = d_in[i];               break;
            case N_NODES:            batch = d_in[i];               break;
            case N_FEAT * HIDDEN:    W1    = (const float*)d_in[i]; break;
            case HIDDEN * HIDDEN:    W2    = (const float*)d_in[i]; break;
            case HIDDEN * N_CLASSES: Wc    = (const float*)d_in[i]; break;
            case N_CLASSES:          bc    = (const float*)d_in[i]; break;
            case HIDDEN: if (n64 < 10) v64[n64++] = (const float*)d_in[i]; break;
        }
    }
    const float *b1 = v64[0], *gm1 = v64[1], *bt1 = v64[2], *rm1 = v64[3], *rv1 = v64[4];
    const float *b2 = v64[5], *gm2 = v64[6], *bt2 = v64[7], *rm2 = v64[8], *rv2 = v64[9];
    float* out = (float*)d_out;

    const int TB = 256;
    int nodeBlocks = (N_NODES + TB - 1) / TB;          // 391
    int edgeBlocks = (N_EDGES + TB - 1) / TB;          // 12500
    int gemmBlocks = (N_NODES + 63) / 64;              // 1563
    int convBlocks = (N_NODES * 32 + TB - 1) / TB;     // 12500 (warp per node)

    k_pre<<<1, 512>>>(ei, batch, b1, gm1, bt1, rm1, rv1, b2, gm2, bt2, rm2, rv2);
    k_init<<<nodeBlocks, TB>>>();
    k_hist<<<edgeBlocks, TB>>>(ei);
    k_scanA<<<SCAN_NB, SCAN_BS>>>();
    k_scanB<<<1, 128>>>();
    k_fill<<<edgeBlocks, TB>>>(ei);

    k_gemm_tc<N_FEAT, 0><<<gemmBlocks, 128>>>(x, W1, N_NODES);
    k_conv<1><<<convBlocks, TB>>>();
    k_gemm_tc<HIDDEN, 1><<<gemmBlocks, 128>>>(nullptr, W2, N_NODES);
    k_conv<2><<<convBlocks, TB>>>();
    k_pool<<<N_GRAPHS, 256>>>(Wc, bc, out);
}

// round 13
// speedup vs baseline: 1.4955x; 1.4955x over previous
#include <cuda_runtime.h>
#include <cuda_fp16.h>
#include <math.h>
#include <stdint.h>

// ---------------- problem constants ----------------
#define N_NODES   100000
#define N_EDGES   3200000
#define N_FEAT    128
#define HIDDEN    64
#define N_CLASSES 3
#define N_GRAPHS  512
#define BN_EPS    1e-5f

#define SCAN_BS   1024
#define SCAN_NB   ((N_NODES + SCAN_BS - 1) / SCAN_BS)   // 98

// ---------------- device scratch (no allocation allowed) ----------------
__device__ __align__(16) __half g_hs[(size_t)N_NODES * HIDDEN];  // dinv-scaled fp16 rows (conv gather input)
__device__ __align__(16) float  g_h2[(size_t)N_NODES * HIDDEN];  // conv output fp32 (gemm2 input / pool input)
__device__ int      g_csr_src[N_EDGES];
__device__ uint32_t g_dp[N_EDGES];    // packed (dst<<15 | pos) recorded by hist
__device__ int      g_ptr[N_NODES];   // block-local exclusive scan (finalized via g_bsum)
__device__ int      g_cnt[N_NODES];   // in-degree (no self loop)
__device__ float    g_dinv[N_NODES];
__device__ int      g_bsum[SCAN_NB + 1];
__device__ int      g_gstart[N_GRAPHS + 1];
__device__ __align__(16) float g_bnA1[HIDDEN], g_bnB1[HIDDEN], g_bnA2[HIDDEN], g_bnB2[HIDDEN];
__device__ int      g_idx64;          // 1 if edge/batch buffers are int64, 0 if int32

__device__ __forceinline__ int load_idx(const void* p, size_t i) {
    if (g_idx64) return (int)((const long long*)p)[i];
    return ((const int*)p)[i];
}

__device__ __forceinline__ uint32_t f2tf32(float x) {
    uint32_t y;
    asm("cvt.rna.tf32.f32 %0, %1;" : "=r"(y) : "f"(x));
    return y;
}

__device__ __forceinline__ int ptr_of(int n) {
    if (n >= N_NODES) return N_EDGES;
    return g_ptr[n] + g_bsum[n >> 10];
}

// ---------------- init: zero degree counters ----------------
__global__ void k_init() {
    int i = blockIdx.x * blockDim.x + threadIdx.x;
    if (i < N_NODES) g_cnt[i] = 0;
}

// ---------------- fused prep (single block, 512 thr): detect + graph starts + bnprep ----------------
__global__ void k_pre(const void* __restrict__ ei, const void* __restrict__ batch,
                      const float* b1, const float* gm1, const float* bt1,
                      const float* rm1, const float* rv1,
                      const float* b2, const float* gm2, const float* bt2,
                      const float* rm2, const float* rv2) {
    int t = threadIdx.x;
    if (t < 32) {
        const long long* p = (const long long*)ei;
        int bad = 0;
        if (t < 16) {
            long long v = p[t];
            bad = (v < 0 || v >= N_NODES);
        }
        unsigned m = __ballot_sync(0xffffffffu, bad);
        if (t == 0) g_idx64 = (m == 0u);
    }
    __syncthreads();
    if (t < N_GRAPHS) {
        int g = t;
        int lo = 0, hi = N_NODES;
        while (lo < hi) { int m = (lo + hi) >> 1; if (load_idx(batch, m) < g) lo = m + 1; else hi = m; }
        g_gstart[t] = lo;
    }
    if (t == 0) g_gstart[N_GRAPHS] = N_NODES;
    if (t < HIDDEN) {
        float a1 = gm1[t] * rsqrtf(rv1[t] + BN_EPS);
        g_bnA1[t] = a1;
        g_bnB1[t] = (b1[t] - rm1[t]) * a1 + bt1[t];
        float a2 = gm2[t] * rsqrtf(rv2[t] + BN_EPS);
        g_bnA2[t] = a2;
        g_bnB2[t] = (b2[t] - rm2[t]) * a2 + bt2[t];
    }
}

// ---------------- histogram of dst; record packed (dst,pos) ----------------
__global__ void k_hist(const void* __restrict__ ei) {
    int e = blockIdx.x * blockDim.x + threadIdx.x;
    if (e < N_EDGES) {
        int d = load_idx(ei, (size_t)N_EDGES + e);
        uint32_t pos = (uint32_t)atomicAdd(&g_cnt[d], 1);
        g_dp[e] = ((uint32_t)d << 15) | pos;
    }
}

// ---------------- scan: block-local exclusive (+dinv fused), then block-sum scan ----------------
__global__ void k_scanA() {
    __shared__ int sm[SCAN_BS];
    int i = blockIdx.x * SCAN_BS + threadIdx.x;
    int v = (i < N_NODES) ? g_cnt[i] : 0;
    if (i < N_NODES) g_dinv[i] = rsqrtf((float)(v + 1));
    sm[threadIdx.x] = v;
    __syncthreads();
    for (int off = 1; off < SCAN_BS; off <<= 1) {
        int t = (threadIdx.x >= off) ? sm[threadIdx.x - off] : 0;
        __syncthreads();
        sm[threadIdx.x] += t;
        __syncthreads();
    }
    if (i < N_NODES) g_ptr[i] = sm[threadIdx.x] - v;
    if (threadIdx.x == SCAN_BS - 1) g_bsum[blockIdx.x] = sm[SCAN_BS - 1];
}

__global__ void k_scanB() {
    __shared__ int sm[128];
    int t = threadIdx.x;
    int v = (t < SCAN_NB) ? g_bsum[t] : 0;
    sm[t] = v;
    __syncthreads();
    for (int off = 1; off < 128; off <<= 1) {
        int u = (t >= off) ? sm[t - off] : 0;
        __syncthreads();
        sm[t] += u;
        __syncthreads();
    }
    if (t < SCAN_NB) g_bsum[t] = sm[t] - v;
}

// ---------------- fill CSR: atomic-free ----------------
__global__ void k_fill(const void* __restrict__ ei) {
    int e = blockIdx.x * blockDim.x + threadIdx.x;
    if (e < N_EDGES) {
        int s = load_idx(ei, e);
        uint32_t dp = g_dp[e];
        int d   = (int)(dp >> 15);
        int pos = (int)(dp & 0x7fffu);
        g_csr_src[g_ptr[d] + g_bsum[d >> 10] + pos] = s;
    }
}

// ---------------- tensor-core GEMM (tf32 mma.sync m16n8k8) ----------------
// g_hs[M,64](fp16) = (A[M,K] @ W[K,64]) * dinv[row]
template<int K, int SRC>
__global__ void k_gemm_tc(const float* __restrict__ Aext, const float* __restrict__ W,
                          int M) {
    __shared__ uint32_t sA[64 * 68];
    __shared__ uint32_t sW[64 * 72];
    const float* A = (SRC == 0) ? Aext : g_h2;
    int row0 = blockIdx.x * 64;
    int t    = threadIdx.x;
    int w    = t >> 5;
    int lane = t & 31;
    int g    = lane >> 2;
    int tig  = lane & 3;

    float acc[8][4];
    #pragma unroll
    for (int nt = 0; nt < 8; nt++)
        #pragma unroll
        for (int j = 0; j < 4; j++) acc[nt][j] = 0.0f;

    for (int k0 = 0; k0 < K; k0 += 64) {
        for (int i = t; i < 64 * 16; i += 128) {
            int r = i >> 4;
            int c = (i & 15) << 2;
            float4 v = *(const float4*)(W + (size_t)(k0 + r) * 64 + c);
            sW[r * 72 + c + 0] = f2tf32(v.x);
            sW[r * 72 + c + 1] = f2tf32(v.y);
            sW[r * 72 + c + 2] = f2tf32(v.z);
            sW[r * 72 + c + 3] = f2tf32(v.w);
        }
        for (int i = t; i < 64 * 16; i += 128) {
            int r = i >> 4;
            int c = (i & 15) << 2;
            int row = row0 + r;
            float4 v = make_float4(0.f, 0.f, 0.f, 0.f);
            if (row < M) v = *(const float4*)(A + (size_t)row * K + k0 + c);
            sA[r * 68 + c + 0] = f2tf32(v.x);
            sA[r * 68 + c + 1] = f2tf32(v.y);
            sA[r * 68 + c + 2] = f2tf32(v.z);
            sA[r * 68 + c + 3] = f2tf32(v.w);
        }
        __syncthreads();
        #pragma unroll
        for (int kc = 0; kc < 8; kc++) {
            int kk = kc * 8;
            uint32_t a0 = sA[(w * 16 + g)     * 68 + kk + tig];
            uint32_t a1 = sA[(w * 16 + g + 8) * 68 + kk + tig];
            uint32_t a2 = sA[(w * 16 + g)     * 68 + kk + tig + 4];
            uint32_t a3 = sA[(w * 16 + g + 8) * 68 + kk + tig + 4];
            #pragma unroll
            for (int nt = 0; nt < 8; nt++) {
                uint32_t b0 = sW[(kk + tig)     * 72 + nt * 8 + g];
                uint32_t b1 = sW[(kk + tig + 4) * 72 + nt * 8 + g];
                asm volatile(
                    "mma.sync.aligned.m16n8k8.row.col.f32.tf32.tf32.f32 "
                    "{%0,%1,%2,%3}, {%4,%5,%6,%7}, {%8,%9}, {%0,%1,%2,%3};"
                    : "+f"(acc[nt][0]), "+f"(acc[nt][1]), "+f"(acc[nt][2]), "+f"(acc[nt][3])
                    : "r"(a0), "r"(a1), "r"(a2), "r"(a3), "r"(b0), "r"(b1));
            }
        }
        __syncthreads();
    }
    int r0 = row0 + w * 16 + g;
    int r1 = r0 + 8;
    if (r0 < M) {
        float d = g_dinv[r0];
        #pragma unroll
        for (int nt = 0; nt < 8; nt++) {
            __half2 v = __floats2half2_rn(acc[nt][0] * d, acc[nt][1] * d);
            *(__half2*)(g_hs + (size_t)r0 * 64 + nt * 8 + 2 * tig) = v;
        }
    }
    if (r1 < M) {
        float d = g_dinv[r1];
        #pragma unroll
        for (int nt = 0; nt < 8; nt++) {
            __half2 v = __floats2half2_rn(acc[nt][2] * d, acc[nt][3] * d);
            *(__half2*)(g_hs + (size_t)r1 * 64 + nt * 8 + 2 * tig) = v;
        }
    }
}

// ---------------- conv (pull, warp-per-node) — proven R9 form ----------------
// reads g_hs (fp16, dinv-scaled); writes g_h2[n] = relu(dinv[n]*(sum+self)*A + B)
template<int LAYER>
__global__ void k_conv() {
    int warp = (blockIdx.x * blockDim.x + threadIdx.x) >> 5;
    int lane = threadIdx.x & 31;
    if (warp >= N_NODES) return;
    int n = warp;
    const __half2* hin = (const __half2*)g_hs;

    float2 acc = make_float2(0.f, 0.f);
    int start = ptr_of(n);
    int end   = ptr_of(n + 1);

    int e = start;
    for (; e + 32 <= end; e += 32) {
        int s = g_csr_src[e + lane];
        #pragma unroll
        for (int j = 0; j < 32; j++) {
            int sj = __shfl_sync(0xffffffffu, s, j);
            float2 hv = __half22float2(hin[(size_t)sj * 32 + lane]);
            acc.x += hv.x;
            acc.y += hv.y;
        }
    }
    int rem = end - e;
    if (rem > 0) {
        int s = (lane < rem) ? g_csr_src[e + lane] : 0;
        for (int j = 0; j < rem; j++) {
            int sj = __shfl_sync(0xffffffffu, s, j);
            float2 hv = __half22float2(hin[(size_t)sj * 32 + lane]);
            acc.x += hv.x;
            acc.y += hv.y;
        }
    }
    // self loop (hs[n] already carries dinv[n])
    {
        float2 hv = __half22float2(hin[(size_t)n * 32 + lane]);
        acc.x += hv.x;
        acc.y += hv.y;
    }
    float dn = g_dinv[n];
    const float* bnA = (LAYER == 1) ? g_bnA1 : g_bnA2;
    const float* bnB = (LAYER == 1) ? g_bnB1 : g_bnB2;
    float2 A = ((const float2*)bnA)[lane];
    float2 B = ((const float2*)bnB)[lane];
    float v0 = fmaxf(acc.x * dn * A.x + B.x, 0.f);
    float v1 = fmaxf(acc.y * dn * A.y + B.y, 0.f);
    ((float2*)g_h2)[(size_t)n * 32 + lane] = make_float2(v0, v1);
}

// ---------------- pool + classifier (block per graph, atomic-free) ----------------
__global__ void k_pool(const float* __restrict__ Wc, const float* __restrict__ bc,
                       float* __restrict__ out) {
    __shared__ float sm[256];
    int g = blockIdx.x;
    int t = threadIdx.x;
    int f   = t & 63;
    int grp = t >> 6;    // 4 row groups
    int s  = g_gstart[g];
    int eN = g_gstart[g + 1];
    float sum = 0.0f;
    for (int n = s + grp; n < eN; n += 4) sum += g_h2[(size_t)n * 64 + f];
    sm[t] = sum;
    __syncthreads();
    if (t < 64) {
        float tot = sm[t] + sm[t + 64] + sm[t + 128] + sm[t + 192];
        sm[t] = tot * (1.0f / fmaxf((float)(eN - s), 1.0f));
    }
    __syncthreads();
    if (t < N_CLASSES) {
        float o = bc[t];
        #pragma unroll
        for (int f2 = 0; f2 < HIDDEN; f2++) o += sm[f2] * Wc[f2 * N_CLASSES + t];
        out[g * N_CLASSES + t] = o;
    }
}

// ---------------- launch ----------------
extern "C" void kernel_launch(void* const* d_in, const int* in_sizes, int n_in,
                              void* d_out, int out_size) {
    const float *x = 0, *W1 = 0, *W2 = 0, *Wc = 0, *bc = 0;
    const void  *ei = 0, *batch = 0;
    const float* v64[10] = {0};
    int n64 = 0;
    for (int i = 0; i < n_in; i++) {
        switch (in_sizes[i]) {
            case N_NODES * N_FEAT:   x     = (const float*)d_in[i]; break;
            case 2 * N_EDGES:        ei    = d_in[i];               break;
            case N_NODES:            batch = d_in[i];               break;
            case N_FEAT * HIDDEN:    W1    = (const float*)d_in[i]; break;
            case HIDDEN * HIDDEN:    W2    = (const float*)d_in[i]; break;
            case HIDDEN * N_CLASSES: Wc    = (const float*)d_in[i]; break;
            case N_CLASSES:          bc    = (const float*)d_in[i]; break;
            case HIDDEN: if (n64 < 10) v64[n64++] = (const float*)d_in[i]; break;
        }
    }
    const float *b1 = v64[0], *gm1 = v64[1], *bt1 = v64[2], *rm1 = v64[3], *rv1 = v64[4];
    const float *b2 = v64[5], *gm2 = v64[6], *bt2 = v64[7], *rm2 = v64[8], *rv2 = v64[9];
    float* out = (float*)d_out;

    const int TB = 256;
    int nodeBlocks = (N_NODES + TB - 1) / TB;          // 391
    int edgeBlocks = (N_EDGES + TB - 1) / TB;          // 12500
    int gemmBlocks = (N_NODES + 63) / 64;              // 1563
    int convBlocks = (N_NODES * 32 + TB - 1) / TB;     // 12500 (warp per node)

    k_pre<<<1, 512>>>(ei, batch, b1, gm1, bt1, rm1, rv1, b2, gm2, bt2, rm2, rv2);
    k_init<<<nodeBlocks, TB>>>();
    k_hist<<<edgeBlocks, TB>>>(ei);
    k_scanA<<<SCAN_NB, SCAN_BS>>>();
    k_scanB<<<1, 128>>>();
    k_fill<<<edgeBlocks, TB>>>(ei);

    k_gemm_tc<N_FEAT, 0><<<gemmBlocks, 128>>>(x, W1, N_NODES);
    k_conv<1><<<convBlocks, TB>>>();
    k_gemm_tc<HIDDEN, 1><<<gemmBlocks, 128>>>(nullptr, W2, N_NODES);
    k_conv<2><<<convBlocks, TB>>>();
    k_pool<<<N_GRAPHS, 256>>>(Wc, bc, out);
}